// round 15
// baseline (speedup 1.0000x reference)
#include <cuda_runtime.h>
#include <cuda_bf16.h>
#include <cuda_fp16.h>
#include <cstdint>

#define B_ROWS 2048
#define CDIM   65536
#define DK     256
#define NNEG   50
#define CAP    6144
#define NTILES 512                 // 128-wide N tiles

// ---------------- device global scratch (no allocation calls) --------------
__device__ __half g_hs[(size_t)B_ROWS * CDIM];             // 256 MB fp16 scores
__device__ float g_tilemax[(size_t)B_ROWS * NTILES];       // 4 MB (lab-excluded)
__device__ float g_rowloss[B_ROWS];
__device__ int   g_lab[B_ROWS];
__device__ __half g_ah[(size_t)B_ROWS * DK];               // A fp16
__device__ __half g_bh[(size_t)CDIM * DK];                 // B fp16 (32 MB)

// ---------------- PTX helpers (baseline ISA only) --------------------------
__device__ __forceinline__ uint32_t smem_u32(const void* p) {
    uint32_t a;
    asm("{ .reg .u64 t; cvta.to.shared.u64 t, %1; cvt.u32.u64 %0, t; }"
        : "=r"(a) : "l"(p));
    return a;
}
__device__ __forceinline__ void cpa16(uint32_t dst, const void* src) {
    asm volatile("cp.async.cg.shared.global [%0], [%1], 16;"
                 :: "r"(dst), "l"(__cvta_generic_to_global(src)));
}
#define CPA_COMMIT() asm volatile("cp.async.commit_group;" ::: "memory")
#define CPA_WAIT0()  asm volatile("cp.async.wait_group 0;" ::: "memory")
#define CPA_WAIT1()  asm volatile("cp.async.wait_group 1;" ::: "memory")
#define CPA_WAIT2()  asm volatile("cp.async.wait_group 2;" ::: "memory")
#define CPA_WAIT3()  asm volatile("cp.async.wait_group 3;" ::: "memory")
#define CPA_WAIT4()  asm volatile("cp.async.wait_group 4;" ::: "memory")

#define LDSM4(r, addr)                                                         \
    asm volatile("ldmatrix.sync.aligned.m8n8.x4.shared.b16 {%0,%1,%2,%3},[%4];"\
        : "=r"((r)[0]), "=r"((r)[1]), "=r"((r)[2]), "=r"((r)[3]) : "r"(addr))

#define MMA16816(d, a, b0, b1)                                                 \
    asm volatile("mma.sync.aligned.m16n8k16.row.col.f32.f16.f16.f32 "          \
        "{%0,%1,%2,%3},{%4,%5,%6,%7},{%8,%9},{%0,%1,%2,%3};"                   \
        : "+f"((d)[0]), "+f"((d)[1]), "+f"((d)[2]), "+f"((d)[3])               \
        : "r"((a)[0]), "r"((a)[1]), "r"((a)[2]), "r"((a)[3]),                  \
          "r"(b0), "r"(b1))

__device__ __forceinline__ uint32_t pkh(__half a, __half b) {
    __half2 p; p.x = a; p.y = b;
    return *(uint32_t*)&p;
}
__device__ __forceinline__ void stcs32(__half* p, uint32_t v) {
    __stcs((unsigned int*)p, v);
}

// ---------------- misc helpers ---------------------------------------------
__device__ __forceinline__ unsigned monof(float v) {
    unsigned b = __float_as_uint(v);
    return (b & 0x80000000u) ? ~b : (b | 0x80000000u);
}
__device__ __forceinline__ float unmonof(unsigned u) {
    unsigned b = (u & 0x80000000u) ? (u & 0x7fffffffu) : ~u;
    return __uint_as_float(b);
}
__device__ __forceinline__ int blockSumI(int v, int* sred, int tid) {
#pragma unroll
    for (int o = 16; o; o >>= 1) v += __shfl_xor_sync(0xffffffffu, v, o);
    if ((tid & 31) == 0) sred[tid >> 5] = v;
    __syncthreads();
    int tot = 0;
#pragma unroll
    for (int w = 0; w < 8; w++) tot += sred[w];
    __syncthreads();
    return tot;
}
__device__ __forceinline__ float blockSumF(float v, float* sred, int tid) {
#pragma unroll
    for (int o = 16; o; o >>= 1) v += __shfl_xor_sync(0xffffffffu, v, o);
    if ((tid & 31) == 0) sred[tid >> 5] = v;
    __syncthreads();
    float tot = 0.f;
#pragma unroll
    for (int w = 0; w < 8; w++) tot += sred[w];
    __syncthreads();
    return tot;
}
__device__ __forceinline__ float blockMinF(float v, float* sred, int tid) {
#pragma unroll
    for (int o = 16; o; o >>= 1) v = fminf(v, __shfl_xor_sync(0xffffffffu, v, o));
    if ((tid & 31) == 0) sred[tid >> 5] = v;
    __syncthreads();
    float tot = sred[0];
#pragma unroll
    for (int w = 1; w < 8; w++) tot = fminf(tot, sred[w]);
    __syncthreads();
    return tot;
}

// ===========================================================================
// Kernel 0: decode labels (int64 vs int32 ambiguity) + clamp
// ===========================================================================
__global__ void k_declab(const void* __restrict__ labp) {
    __shared__ int s_nz;
    const unsigned* w = (const unsigned*)labp;
    if (threadIdx.x == 0) s_nz = 0;
    __syncthreads();
    int nz = 0;
    for (int i = threadIdx.x; i < B_ROWS / 2; i += 256)
        if (w[2 * i + 1] != 0u) nz = 1;
    if (nz) atomicOr(&s_nz, 1);
    __syncthreads();
    bool is64 = (s_nz == 0);
    for (int r = threadIdx.x; r < B_ROWS; r += 256) {
        long long v = is64 ? ((const long long*)labp)[r] : (long long)((const int*)labp)[r];
        if (v < 0) v = 0;
        if (v > CDIM - 1) v = CDIM - 1;
        g_lab[r] = (int)v;
    }
}

// ===========================================================================
// Kernel 0b: fp32 -> fp16 conversion (round-to-nearest)
// ===========================================================================
__global__ __launch_bounds__(256) void k_conv(const float* __restrict__ S,
                                              __half* __restrict__ H) {
    size_t i = (size_t)blockIdx.x * 256 + threadIdx.x;  // one float4 each
    float4 v = ((const float4*)S)[i];
    ((uint2*)H)[i] = make_uint2(
        pkh(__float2half(v.x), __float2half(v.y)),
        pkh(__float2half(v.z), __float2half(v.w)));
}

// ===========================================================================
// Kernel 1: HMMA GEMM. CTA tile 128(M)x128(N), 4 warps 2x2 (warp 64x64),
// 128 threads, 2 CTA/SM. Pure fp16 single pass, fp32 accumulate.
// 6-stage cp.async pipeline (prefetch distance 5), ONE __syncthreads/stage.
// Stage = k-chunk of 32, XOR-swizzled 64B rows (piece ^= (row>>1)&3):
//   A 0, B 8192   (16384/stage, x6 = 96KB/CTA)
// Epilogue: fp16 streaming score store + lab-excluded per-row tile max
// (max taken over the ROUNDED values so topk sees a consistent world).
// ===========================================================================
__global__ __launch_bounds__(128, 2) void k_gemm_mma() {
    extern __shared__ __align__(16) char smem[];
    const uint32_t sb = smem_u32(smem);
    const int tid = threadIdx.x, lane = tid & 31, wid = tid >> 5;
    const int wm = wid & 1, wn = wid >> 1;          // warp grid 2(M) x 2(N)
    const int g = lane >> 2, tig = lane & 3;
    const int m0 = blockIdx.x * 128;
    const int n0t = blockIdx.y;                      // 128-wide N tile index

    float acc[4][8][4] = {};                         // [mi][ni][4]

    // loader lane mapping: 128 threads, row 0..63 (+64), 2 pieces each
    const int lrow = tid >> 1, lpc2 = (tid & 1) * 2;

    // ldmatrix lane constants (xor term is lane-constant within each frag)
    const int r15 = lane & 15, khalf = (lane >> 4) & 1;
    const uint32_t aBase = (uint32_t)((wm * 64 + r15) * 64);
    const uint32_t aS0 = (uint32_t)(((khalf) ^ ((r15 >> 1) & 3)) * 16);
    const int rb = (lane & 7) + ((lane >> 4) & 1) * 8, kbh = (lane >> 3) & 1;
    const uint32_t bBase = (uint32_t)((wn * 64 + rb) * 64);
    const uint32_t bS0 = (uint32_t)(((kbh) ^ ((rb >> 1) & 3)) * 16);

#define LOAD_STAGE(kt, bufi)                                                   \
    do {                                                                       \
        uint32_t st_ = sb + (bufi) * 16384;                                    \
        _Pragma("unroll")                                                      \
        for (int h_ = 0; h_ < 2; h_++) {                                       \
            int r_ = lrow + h_ * 64;                                           \
            uint32_t rs_ = st_ + r_ * 64;                                      \
            uint32_t sw_ = ((r_ >> 1) & 3);                                    \
            _Pragma("unroll")                                                  \
            for (int pp_ = 0; pp_ < 2; pp_++) {                                \
                int pc_ = lpc2 + pp_;                                          \
                int kof_ = (kt) * 32 + pc_ * 8;                                \
                uint32_t so_ = rs_ + ((pc_ ^ sw_) * 16);                       \
                cpa16(so_ +    0, g_ah + (size_t)(m0 + r_) * DK + kof_);       \
                cpa16(so_ + 8192, g_bh + (size_t)(n0t * 128 + r_) * DK + kof_);\
            }                                                                  \
        }                                                                      \
        CPA_COMMIT();                                                          \
    } while (0)

    LOAD_STAGE(0, 0);
    LOAD_STAGE(1, 1);
    LOAD_STAGE(2, 2);
    LOAD_STAGE(3, 3);
    LOAD_STAGE(4, 4);

#pragma unroll 1
    for (int kt = 0; kt < 8; kt++) {
        if (kt <= 3)      CPA_WAIT4();
        else if (kt == 4) CPA_WAIT3();
        else if (kt == 5) CPA_WAIT2();
        else if (kt == 6) CPA_WAIT1();
        else              CPA_WAIT0();
        __syncthreads();
        if (kt + 5 < 8) LOAD_STAGE(kt + 5, (kt + 5) % 6);

        const uint32_t st = sb + (kt % 6) * 16384;
#pragma unroll
        for (int kk = 0; kk < 2; kk++) {
            const uint32_t aS = kk ? (aS0 ^ 32) : aS0;
            const uint32_t bS = kk ? (bS0 ^ 32) : bS0;
            uint32_t a[4][4], bh[8][2];
#pragma unroll
            for (int mi = 0; mi < 4; mi++)
                LDSM4(a[mi], st + aBase + mi * 1024 + aS);
#pragma unroll
            for (int p = 0; p < 4; p++) {
                uint32_t r4[4];
                LDSM4(r4, st + 8192 + bBase + p * 1024 + bS);
                bh[2 * p][0] = r4[0]; bh[2 * p][1] = r4[1];
                bh[2 * p + 1][0] = r4[2]; bh[2 * p + 1][1] = r4[3];
            }
#pragma unroll
            for (int mi = 0; mi < 4; mi++)
#pragma unroll
                for (int ni = 0; ni < 8; ni++)
                    MMA16816(acc[mi][ni], a[mi], bh[ni][0], bh[ni][1]);
        }
    }
#undef LOAD_STAGE
    __syncthreads();   // smem reuse for the reduction below

    // ---- epilogue: fp16 score store + lab-excluded row max (over the
    //      ROUNDED values, so k_topk's theta is exactly consistent) ----
    float* sf = (float*)smem;  // [2 wn][128 rows]
#pragma unroll
    for (int mi = 0; mi < 4; mi++) {
        int row0 = m0 + wm * 64 + mi * 16 + g;
        int row1 = row0 + 8;
        int lab0 = g_lab[row0], lab1 = g_lab[row1];
        float mx0 = -3.402823466e38f, mx1 = -3.402823466e38f;
#pragma unroll
        for (int ni = 0; ni < 8; ni++) {
            int col = n0t * 128 + wn * 64 + ni * 8 + tig * 2;
            __half h0 = __float2half(acc[mi][ni][0]);
            __half h1 = __float2half(acc[mi][ni][1]);
            __half h2 = __float2half(acc[mi][ni][2]);
            __half h3 = __float2half(acc[mi][ni][3]);
            stcs32(g_hs + (size_t)row0 * CDIM + col, pkh(h0, h1));
            stcs32(g_hs + (size_t)row1 * CDIM + col, pkh(h2, h3));
            float r0 = __half2float(h0), r1 = __half2float(h1);
            float r2 = __half2float(h2), r3 = __half2float(h3);
            if (col != lab0)     mx0 = fmaxf(mx0, r0);
            if (col + 1 != lab0) mx0 = fmaxf(mx0, r1);
            if (col != lab1)     mx1 = fmaxf(mx1, r2);
            if (col + 1 != lab1) mx1 = fmaxf(mx1, r3);
        }
#pragma unroll
        for (int o = 1; o <= 2; o <<= 1) {
            mx0 = fmaxf(mx0, __shfl_xor_sync(0xffffffffu, mx0, o));
            mx1 = fmaxf(mx1, __shfl_xor_sync(0xffffffffu, mx1, o));
        }
        if (tig == 0) {
            sf[wn * 128 + wm * 64 + mi * 16 + g]     = mx0;
            sf[wn * 128 + wm * 64 + mi * 16 + g + 8] = mx1;
        }
    }
    __syncthreads();
    if (tid < 128) {
        float m = fmaxf(sf[tid], sf[128 + tid]);
        g_tilemax[(size_t)(m0 + tid) * NTILES + n0t] = m;
    }
}

// ===========================================================================
// Kernel 2: per row -> exact top-50 negatives over the fp16 score world.
// Pass A: 512 lab-excluded tile maxima (2KB/row) -> theta. Pass B: scan
// ONLY tiles with tilemax >= theta, compact candidates, binary search on
// monotone keys. One 256-thread block per row.
// Each warp covers EXACTLY one 128-col tile: 32 lanes x 4 halves (uint2).
// ===========================================================================
__global__ __launch_bounds__(256) void k_topk() {
    const int row = blockIdx.x;
    const int tid = threadIdx.x;
    const __half* rp = g_hs + (size_t)row * CDIM;
    const int lab = g_lab[row];

    __shared__ float    s_max[256];
    __shared__ unsigned s_list[CAP];
    __shared__ unsigned short s_tiles[NTILES];
    __shared__ unsigned s_cnt, s_nt;
    __shared__ int      s_ired[8];
    __shared__ float    s_fred[8];

    // ---- pass A: thread max over 2 tile-maxima ----
    const float2* tm2 = (const float2*)(g_tilemax + (size_t)row * NTILES);
    float2 tv = tm2[tid];
    float lmax = fmaxf(tv.x, tv.y);
    s_max[tid] = lmax;
    __syncthreads();

    float gmax = -3.402823466e38f;
    int c = 0;
#pragma unroll 8
    for (int j = 0; j < 256; j++) {
        float m = s_max[j];
        gmax = fmaxf(gmax, m);
        c += (m > lmax);
    }
    float cand = (c < NNEG) ? lmax : 3.402823466e38f;
    float theta = blockMinF(cand, s_fred, tid);   // <= v50, count(>=theta) >= 50

    float posv = __half2float(rp[lab]);
    float M = fmaxf(gmax, posv);
    if (tid == 0) { s_cnt = 0; s_nt = 0; }
    __syncthreads();

    // ---- pass B: list hot tiles, then warp-per-tile candidate compaction ----
    if (tv.x >= theta) { unsigned p = atomicAdd(&s_nt, 1u); s_tiles[p] = (unsigned short)(2 * tid); }
    if (tv.y >= theta) { unsigned p = atomicAdd(&s_nt, 1u); s_tiles[p] = (unsigned short)(2 * tid + 1); }
    __syncthreads();
    const int nt = (int)s_nt;
    const int lane = tid & 31, w = tid >> 5;
    for (int cb = 0; cb < nt; cb += 8) {
        int li = cb + w;
        if (li < nt) {
            int t = s_tiles[li];
            int base = t * 128 + lane * 4;                 // 4 halves per lane
            uint2 v2 = *(const uint2*)(rp + base);
            unsigned ws[2] = {v2.x, v2.y};
#pragma unroll
            for (int q = 0; q < 2; q++) {
                float2 f = __half22float2(*(__half2*)&ws[q]);
                int c0 = base + 2 * q, c1 = c0 + 1;
                if (f.x >= theta && c0 != lab) { unsigned p = atomicAdd(&s_cnt, 1u); if (p < CAP) s_list[p] = monof(f.x); }
                if (f.y >= theta && c1 != lab) { unsigned p = atomicAdd(&s_cnt, 1u); if (p < CAP) s_list[p] = monof(f.y); }
            }
        }
    }
    __syncthreads();
    unsigned cnt = s_cnt;

    float Sneg, Sexp;

    if (cnt <= CAP) {
        unsigned long long lo = (unsigned long long)monof(theta);
        unsigned long long hi = 0xffffffffull;
        while (lo < hi) {
            unsigned long long mid = lo + (hi - lo + 1) / 2;
            int lc = 0;
            for (unsigned i = tid; i < cnt; i += 256)
                lc += ((unsigned long long)s_list[i] >= mid);
            int tot = blockSumI(lc, s_ired, tid);
            if (tot >= NNEG) lo = mid; else hi = mid - 1;
        }
        unsigned long long ucut = lo + 1;
        int lk1 = 0; float lS = 0.f, lE = 0.f;
        for (unsigned i = tid; i < cnt; i += 256) {
            unsigned long long u = s_list[i];
            if (u >= ucut) {
                float x = unmonof((unsigned)u);
                lk1++; lS += x; lE += expf(x - M);
            }
        }
        int k1 = blockSumI(lk1, s_ired, tid);
        float S1 = blockSumF(lS, s_fred, tid);
        float E1 = blockSumF(lE, s_fred, tid);
        float vstar = unmonof((unsigned)lo);
        float n2 = (float)(NNEG - k1);
        Sneg = S1 + n2 * vstar;
        Sexp = E1 + n2 * expf(vstar - M);
    } else {
        // exact fallback (massive ties): binary search with full-row scans
        unsigned long long lo = (unsigned long long)monof(theta);
        unsigned long long hi = 0xffffffffull;
        while (lo < hi) {
            unsigned long long mid = lo + (hi - lo + 1) / 2;
            int lc = 0;
            for (int i = tid; i < CDIM / 8; i += 256) {
                int base = i * 8;
                uint4 v4 = *(const uint4*)(rp + base);
                unsigned ws[4] = {v4.x, v4.y, v4.z, v4.w};
#pragma unroll
                for (int q = 0; q < 4; q++) {
                    float2 f = __half22float2(*(__half2*)&ws[q]);
                    int c0 = base + 2 * q, c1 = c0 + 1;
                    if (c0 != lab) lc += ((unsigned long long)monof(f.x) >= mid);
                    if (c1 != lab) lc += ((unsigned long long)monof(f.y) >= mid);
                }
            }
            int tot = blockSumI(lc, s_ired, tid);
            if (tot >= NNEG) lo = mid; else hi = mid - 1;
        }
        unsigned long long ucut = lo + 1;
        int lk1 = 0; float lS = 0.f, lE = 0.f;
        for (int i = tid; i < CDIM / 8; i += 256) {
            int base = i * 8;
            uint4 v4 = *(const uint4*)(rp + base);
            unsigned ws[4] = {v4.x, v4.y, v4.z, v4.w};
#pragma unroll
            for (int q = 0; q < 4; q++) {
                float2 f = __half22float2(*(__half2*)&ws[q]);
                int c0 = base + 2 * q, c1 = c0 + 1;
                if (c0 != lab && (unsigned long long)monof(f.x) >= ucut) { lk1++; lS += f.x; lE += expf(f.x - M); }
                if (c1 != lab && (unsigned long long)monof(f.y) >= ucut) { lk1++; lS += f.y; lE += expf(f.y - M); }
            }
        }
        int k1 = blockSumI(lk1, s_ired, tid);
        float S1 = blockSumF(lS, s_fred, tid);
        float E1 = blockSumF(lE, s_fred, tid);
        float vstar = unmonof((unsigned)lo);
        float n2 = (float)(NNEG - k1);
        Sneg = S1 + n2 * vstar;
        Sexp = E1 + n2 * expf(vstar - M);
    }

    if (tid == 0) {
        float lse = M + logf(Sexp + expf(posv - M));
        // targets: t0 = 0.9 + 0.1/500 = 0.9002, tj = 0.0002 (x50), sum = 0.9102
        g_rowloss[row] = 0.9102f * lse - 0.9002f * posv - 0.0002f * Sneg;
    }
}

// ===========================================================================
// Kernel 3: mean over rows -> scalar
// ===========================================================================
__global__ void k_final(float* __restrict__ out) {
    __shared__ float s[256];
    int tid = threadIdx.x;
    float a = 0.f;
    for (int i = tid; i < B_ROWS; i += 256) a += g_rowloss[i];
    s[tid] = a;
    __syncthreads();
    for (int st = 128; st > 0; st >>= 1) {
        if (tid < st) s[tid] += s[tid + st];
        __syncthreads();
    }
    if (tid == 0) out[0] = s[0] * (1.0f / (float)B_ROWS);
}

// ===========================================================================
extern "C" void kernel_launch(void* const* d_in, const int* in_sizes, int n_in,
                              void* d_out, int out_size) {
    const float* f = nullptr;
    const float* cen = nullptr;
    const void* lab = nullptr;
    for (int i = 0; i < n_in; i++) {
        long long sz = in_sizes[i];
        if (sz == (long long)B_ROWS * DK) f = (const float*)d_in[i];
        else if (sz == (long long)CDIM * DK) cen = (const float*)d_in[i];
        else if (sz == (long long)B_ROWS) lab = d_in[i];
    }
    if (!f) f = (const float*)d_in[0];
    if (!cen) cen = (const float*)d_in[1];
    if (!lab) lab = d_in[2];

    const int SMEM_SZ = 6 * 16384;  // six stages of (A|B), 96KB/CTA
    static int s_attr_done = 0;
    if (!s_attr_done) {
        cudaFuncSetAttribute(k_gemm_mma,
                             cudaFuncAttributeMaxDynamicSharedMemorySize, SMEM_SZ);
        s_attr_done = 1;
    }

    __half *ah, *bh;
    cudaGetSymbolAddress((void**)&ah, g_ah);
    cudaGetSymbolAddress((void**)&bh, g_bh);

    k_declab<<<1, 256>>>(lab);
    k_conv<<<(B_ROWS * DK) / (256 * 4), 256>>>(f, ah);
    k_conv<<<(CDIM * DK) / (256 * 4), 256>>>(cen, bh);
    dim3 grid(16, 512);  // x = M tiles (co-resident CTAs share a B tile), y = N
    k_gemm_mma<<<grid, 128, SMEM_SZ>>>();
    k_topk<<<B_ROWS, 256>>>();
    k_final<<<1, 256>>>((float*)d_out);
}

// round 16
// speedup vs baseline: 1.1274x; 1.1274x over previous
#include <cuda_runtime.h>
#include <cuda_bf16.h>
#include <cuda_fp16.h>
#include <cstdint>

#define B_ROWS 2048
#define CDIM   65536
#define DK     256
#define NNEG   50
#define CAP    6144
#define NTILES 512                 // 128-wide N tiles

// ---------------- device global scratch (no allocation calls) --------------
__device__ __half g_hs[(size_t)B_ROWS * CDIM];             // 256 MB fp16 scores
__device__ float g_tilemax[(size_t)B_ROWS * NTILES];       // 4 MB (lab-excluded)
__device__ float g_rowloss[B_ROWS];
__device__ int   g_lab[B_ROWS];
__device__ __half g_ah[(size_t)B_ROWS * DK];               // A fp16
__device__ __half g_bh[(size_t)CDIM * DK];                 // B fp16 (32 MB)

// ---------------- PTX helpers (baseline ISA only) --------------------------
__device__ __forceinline__ uint32_t smem_u32(const void* p) {
    uint32_t a;
    asm("{ .reg .u64 t; cvta.to.shared.u64 t, %1; cvt.u32.u64 %0, t; }"
        : "=r"(a) : "l"(p));
    return a;
}
__device__ __forceinline__ void cpa16(uint32_t dst, const void* src) {
    asm volatile("cp.async.cg.shared.global [%0], [%1], 16;"
                 :: "r"(dst), "l"(__cvta_generic_to_global(src)));
}
#define CPA_COMMIT() asm volatile("cp.async.commit_group;" ::: "memory")
#define CPA_WAIT0()  asm volatile("cp.async.wait_group 0;" ::: "memory")
#define CPA_WAIT1()  asm volatile("cp.async.wait_group 1;" ::: "memory")
#define CPA_WAIT2()  asm volatile("cp.async.wait_group 2;" ::: "memory")
#define CPA_WAIT3()  asm volatile("cp.async.wait_group 3;" ::: "memory")
#define CPA_WAIT4()  asm volatile("cp.async.wait_group 4;" ::: "memory")

#define LDSM4(r, addr)                                                         \
    asm volatile("ldmatrix.sync.aligned.m8n8.x4.shared.b16 {%0,%1,%2,%3},[%4];"\
        : "=r"((r)[0]), "=r"((r)[1]), "=r"((r)[2]), "=r"((r)[3]) : "r"(addr))

#define MMA16816(d, a, b0, b1)                                                 \
    asm volatile("mma.sync.aligned.m16n8k16.row.col.f32.f16.f16.f32 "          \
        "{%0,%1,%2,%3},{%4,%5,%6,%7},{%8,%9},{%0,%1,%2,%3};"                   \
        : "+f"((d)[0]), "+f"((d)[1]), "+f"((d)[2]), "+f"((d)[3])               \
        : "r"((a)[0]), "r"((a)[1]), "r"((a)[2]), "r"((a)[3]),                  \
          "r"(b0), "r"(b1))

__device__ __forceinline__ uint32_t pkh(__half a, __half b) {
    __half2 p; p.x = a; p.y = b;
    return *(uint32_t*)&p;
}
__device__ __forceinline__ void stcs32(__half* p, uint32_t v) {
    __stcs((unsigned int*)p, v);
}

// ---------------- misc helpers ---------------------------------------------
__device__ __forceinline__ unsigned monof(float v) {
    unsigned b = __float_as_uint(v);
    return (b & 0x80000000u) ? ~b : (b | 0x80000000u);
}
__device__ __forceinline__ float unmonof(unsigned u) {
    unsigned b = (u & 0x80000000u) ? (u & 0x7fffffffu) : ~u;
    return __uint_as_float(b);
}
__device__ __forceinline__ int blockSumI(int v, int* sred, int tid) {
#pragma unroll
    for (int o = 16; o; o >>= 1) v += __shfl_xor_sync(0xffffffffu, v, o);
    if ((tid & 31) == 0) sred[tid >> 5] = v;
    __syncthreads();
    int tot = 0;
#pragma unroll
    for (int w = 0; w < 8; w++) tot += sred[w];
    __syncthreads();
    return tot;
}
__device__ __forceinline__ float blockSumF(float v, float* sred, int tid) {
#pragma unroll
    for (int o = 16; o; o >>= 1) v += __shfl_xor_sync(0xffffffffu, v, o);
    if ((tid & 31) == 0) sred[tid >> 5] = v;
    __syncthreads();
    float tot = 0.f;
#pragma unroll
    for (int w = 0; w < 8; w++) tot += sred[w];
    __syncthreads();
    return tot;
}
__device__ __forceinline__ float blockMinF(float v, float* sred, int tid) {
#pragma unroll
    for (int o = 16; o; o >>= 1) v = fminf(v, __shfl_xor_sync(0xffffffffu, v, o));
    if ((tid & 31) == 0) sred[tid >> 5] = v;
    __syncthreads();
    float tot = sred[0];
#pragma unroll
    for (int w = 1; w < 8; w++) tot = fminf(tot, sred[w]);
    __syncthreads();
    return tot;
}

// ===========================================================================
// Kernel 0: decode labels (int64 vs int32 ambiguity) + clamp
// ===========================================================================
__global__ void k_declab(const void* __restrict__ labp) {
    __shared__ int s_nz;
    const unsigned* w = (const unsigned*)labp;
    if (threadIdx.x == 0) s_nz = 0;
    __syncthreads();
    int nz = 0;
    for (int i = threadIdx.x; i < B_ROWS / 2; i += 256)
        if (w[2 * i + 1] != 0u) nz = 1;
    if (nz) atomicOr(&s_nz, 1);
    __syncthreads();
    bool is64 = (s_nz == 0);
    for (int r = threadIdx.x; r < B_ROWS; r += 256) {
        long long v = is64 ? ((const long long*)labp)[r] : (long long)((const int*)labp)[r];
        if (v < 0) v = 0;
        if (v > CDIM - 1) v = CDIM - 1;
        g_lab[r] = (int)v;
    }
}

// ===========================================================================
// Kernel 0b: fp32 -> fp16 conversion (round-to-nearest)
// ===========================================================================
__global__ __launch_bounds__(256) void k_conv(const float* __restrict__ S,
                                              __half* __restrict__ H) {
    size_t i = (size_t)blockIdx.x * 256 + threadIdx.x;  // one float4 each
    float4 v = ((const float4*)S)[i];
    ((uint2*)H)[i] = make_uint2(
        pkh(__float2half(v.x), __float2half(v.y)),
        pkh(__float2half(v.z), __float2half(v.w)));
}

// ===========================================================================
// Kernel 1: HMMA GEMM. CTA tile 128(M)x128(N), 8 warps 2x4 (warp 64x32),
// 256 threads, 2 CTA/SM (16 warps/SM — latency-hiding floor, per R9+R15).
// Pure fp16 single pass: A * B, fp32 accumulate.
// 6-stage cp.async pipeline (prefetch distance 5), ONE __syncthreads/stage.
// Stage = k-chunk of 32, XOR-swizzled 64B rows (piece ^= (row>>1)&3):
//   A 0, B 8192   (16384/stage, x6 = 96KB/CTA)
// Epilogue: fp16 streaming score store + lab-excluded per-row tile max
// (max over the ROUNDED values so k_topk sees a consistent world).
// ===========================================================================
__global__ __launch_bounds__(256, 2) void k_gemm_mma() {
    extern __shared__ __align__(16) char smem[];
    const uint32_t sb = smem_u32(smem);
    const int tid = threadIdx.x, lane = tid & 31, wid = tid >> 5;
    const int wm = wid & 1, wn = wid >> 1;          // warp grid 2(M) x 4(N)
    const int g = lane >> 2, tig = lane & 3;
    const int m0 = blockIdx.x * 128;
    const int n0t = blockIdx.y;                      // 128-wide N tile index

    float acc[4][4][4] = {};                         // [mi][ni][4]

    // loader lane mapping: row 0..63 (+64), 16B piece 0..3
    const int lrow = tid >> 2, lpc = tid & 3;
    const uint32_t swzL = (uint32_t)((lpc ^ ((lrow >> 1) & 3)) * 16);

    // ldmatrix lane constants (xor term is lane-constant within each frag)
    const int r15 = lane & 15, khalf = (lane >> 4) & 1;
    const uint32_t aBase = (uint32_t)((wm * 64 + r15) * 64);
    const uint32_t aS0 = (uint32_t)(((khalf) ^ ((r15 >> 1) & 3)) * 16);
    const int rb = (lane & 7) + ((lane >> 4) & 1) * 8, kbh = (lane >> 3) & 1;
    const uint32_t bBase = (uint32_t)((wn * 32 + rb) * 64);
    const uint32_t bS0 = (uint32_t)(((kbh) ^ ((rb >> 1) & 3)) * 16);

#define LOAD_STAGE(kt, bufi)                                                   \
    do {                                                                       \
        uint32_t st_ = sb + (bufi) * 16384;                                    \
        int kof_ = (kt) * 32 + lpc * 8;                                        \
        _Pragma("unroll")                                                      \
        for (int h_ = 0; h_ < 2; h_++) {                                       \
            int r_ = lrow + h_ * 64;                                           \
            size_t ga_ = (size_t)(m0 + r_) * DK + kof_;                        \
            size_t gb_ = (size_t)(n0t * 128 + r_) * DK + kof_;                 \
            uint32_t so_ = st_ + r_ * 64 + swzL;                               \
            cpa16(so_ +    0, g_ah + ga_);                                     \
            cpa16(so_ + 8192, g_bh + gb_);                                     \
        }                                                                      \
        CPA_COMMIT();                                                          \
    } while (0)

    LOAD_STAGE(0, 0);
    LOAD_STAGE(1, 1);
    LOAD_STAGE(2, 2);
    LOAD_STAGE(3, 3);
    LOAD_STAGE(4, 4);

#pragma unroll 1
    for (int kt = 0; kt < 8; kt++) {
        if (kt <= 3)      CPA_WAIT4();
        else if (kt == 4) CPA_WAIT3();
        else if (kt == 5) CPA_WAIT2();
        else if (kt == 6) CPA_WAIT1();
        else              CPA_WAIT0();
        __syncthreads();
        if (kt + 5 < 8) LOAD_STAGE(kt + 5, (kt + 5) % 6);

        const uint32_t st = sb + (kt % 6) * 16384;
#pragma unroll
        for (int kk = 0; kk < 2; kk++) {
            const uint32_t aS = kk ? (aS0 ^ 32) : aS0;
            const uint32_t bS = kk ? (bS0 ^ 32) : bS0;
            uint32_t a[4][4], bh[4][2];
#pragma unroll
            for (int mi = 0; mi < 4; mi++)
                LDSM4(a[mi], st + aBase + mi * 1024 + aS);
#pragma unroll
            for (int p = 0; p < 2; p++) {
                uint32_t r4[4];
                LDSM4(r4, st + 8192 + bBase + p * 1024 + bS);
                bh[2 * p][0] = r4[0]; bh[2 * p][1] = r4[1];
                bh[2 * p + 1][0] = r4[2]; bh[2 * p + 1][1] = r4[3];
            }
#pragma unroll
            for (int mi = 0; mi < 4; mi++)
#pragma unroll
                for (int ni = 0; ni < 4; ni++)
                    MMA16816(acc[mi][ni], a[mi], bh[ni][0], bh[ni][1]);
        }
    }
#undef LOAD_STAGE
    __syncthreads();   // smem reuse for the reduction below

    // ---- epilogue: fp16 score store + lab-excluded row max (over the
    //      ROUNDED values, so k_topk's theta is exactly consistent) ----
    float* sf = (float*)smem;  // [4 wn][128 rows]
#pragma unroll
    for (int mi = 0; mi < 4; mi++) {
        int row0 = m0 + wm * 64 + mi * 16 + g;
        int row1 = row0 + 8;
        int lab0 = g_lab[row0], lab1 = g_lab[row1];
        float mx0 = -3.402823466e38f, mx1 = -3.402823466e38f;
#pragma unroll
        for (int ni = 0; ni < 4; ni++) {
            int col = n0t * 128 + wn * 32 + ni * 8 + tig * 2;
            __half h0 = __float2half(acc[mi][ni][0]);
            __half h1 = __float2half(acc[mi][ni][1]);
            __half h2 = __float2half(acc[mi][ni][2]);
            __half h3 = __float2half(acc[mi][ni][3]);
            stcs32(g_hs + (size_t)row0 * CDIM + col, pkh(h0, h1));
            stcs32(g_hs + (size_t)row1 * CDIM + col, pkh(h2, h3));
            float r0 = __half2float(h0), r1 = __half2float(h1);
            float r2 = __half2float(h2), r3 = __half2float(h3);
            if (col != lab0)     mx0 = fmaxf(mx0, r0);
            if (col + 1 != lab0) mx0 = fmaxf(mx0, r1);
            if (col != lab1)     mx1 = fmaxf(mx1, r2);
            if (col + 1 != lab1) mx1 = fmaxf(mx1, r3);
        }
#pragma unroll
        for (int o = 1; o <= 2; o <<= 1) {
            mx0 = fmaxf(mx0, __shfl_xor_sync(0xffffffffu, mx0, o));
            mx1 = fmaxf(mx1, __shfl_xor_sync(0xffffffffu, mx1, o));
        }
        if (tig == 0) {
            sf[wn * 128 + wm * 64 + mi * 16 + g]     = mx0;
            sf[wn * 128 + wm * 64 + mi * 16 + g + 8] = mx1;
        }
    }
    __syncthreads();
    if (tid < 128) {
        float m = fmaxf(fmaxf(sf[tid], sf[128 + tid]),
                        fmaxf(sf[256 + tid], sf[384 + tid]));
        g_tilemax[(size_t)(m0 + tid) * NTILES + n0t] = m;
    }
}

// ===========================================================================
// Kernel 2: per row -> exact top-50 negatives over the fp16 score world.
// Pass A: 512 lab-excluded tile maxima (2KB/row) -> theta. Pass B: scan
// ONLY tiles with tilemax >= theta, compact candidates, binary search on
// monotone keys. One 256-thread block per row.
// Each warp covers EXACTLY one 128-col tile: 32 lanes x 4 halves (uint2).
// ===========================================================================
__global__ __launch_bounds__(256) void k_topk() {
    const int row = blockIdx.x;
    const int tid = threadIdx.x;
    const __half* rp = g_hs + (size_t)row * CDIM;
    const int lab = g_lab[row];

    __shared__ float    s_max[256];
    __shared__ unsigned s_list[CAP];
    __shared__ unsigned short s_tiles[NTILES];
    __shared__ unsigned s_cnt, s_nt;
    __shared__ int      s_ired[8];
    __shared__ float    s_fred[8];

    // ---- pass A: thread max over 2 tile-maxima ----
    const float2* tm2 = (const float2*)(g_tilemax + (size_t)row * NTILES);
    float2 tv = tm2[tid];
    float lmax = fmaxf(tv.x, tv.y);
    s_max[tid] = lmax;
    __syncthreads();

    float gmax = -3.402823466e38f;
    int c = 0;
#pragma unroll 8
    for (int j = 0; j < 256; j++) {
        float m = s_max[j];
        gmax = fmaxf(gmax, m);
        c += (m > lmax);
    }
    float cand = (c < NNEG) ? lmax : 3.402823466e38f;
    float theta = blockMinF(cand, s_fred, tid);   // <= v50, count(>=theta) >= 50

    float posv = __half2float(rp[lab]);
    float M = fmaxf(gmax, posv);
    if (tid == 0) { s_cnt = 0; s_nt = 0; }
    __syncthreads();

    // ---- pass B: list hot tiles, then warp-per-tile candidate compaction ----
    if (tv.x >= theta) { unsigned p = atomicAdd(&s_nt, 1u); s_tiles[p] = (unsigned short)(2 * tid); }
    if (tv.y >= theta) { unsigned p = atomicAdd(&s_nt, 1u); s_tiles[p] = (unsigned short)(2 * tid + 1); }
    __syncthreads();
    const int nt = (int)s_nt;
    const int lane = tid & 31, w = tid >> 5;
    for (int cb = 0; cb < nt; cb += 8) {
        int li = cb + w;
        if (li < nt) {
            int t = s_tiles[li];
            int base = t * 128 + lane * 4;                 // 4 halves per lane
            uint2 v2 = *(const uint2*)(rp + base);
            unsigned ws[2] = {v2.x, v2.y};
#pragma unroll
            for (int q = 0; q < 2; q++) {
                float2 f = __half22float2(*(__half2*)&ws[q]);
                int c0 = base + 2 * q, c1 = c0 + 1;
                if (f.x >= theta && c0 != lab) { unsigned p = atomicAdd(&s_cnt, 1u); if (p < CAP) s_list[p] = monof(f.x); }
                if (f.y >= theta && c1 != lab) { unsigned p = atomicAdd(&s_cnt, 1u); if (p < CAP) s_list[p] = monof(f.y); }
            }
        }
    }
    __syncthreads();
    unsigned cnt = s_cnt;

    float Sneg, Sexp;

    if (cnt <= CAP) {
        unsigned long long lo = (unsigned long long)monof(theta);
        unsigned long long hi = 0xffffffffull;
        while (lo < hi) {
            unsigned long long mid = lo + (hi - lo + 1) / 2;
            int lc = 0;
            for (unsigned i = tid; i < cnt; i += 256)
                lc += ((unsigned long long)s_list[i] >= mid);
            int tot = blockSumI(lc, s_ired, tid);
            if (tot >= NNEG) lo = mid; else hi = mid - 1;
        }
        unsigned long long ucut = lo + 1;
        int lk1 = 0; float lS = 0.f, lE = 0.f;
        for (unsigned i = tid; i < cnt; i += 256) {
            unsigned long long u = s_list[i];
            if (u >= ucut) {
                float x = unmonof((unsigned)u);
                lk1++; lS += x; lE += expf(x - M);
            }
        }
        int k1 = blockSumI(lk1, s_ired, tid);
        float S1 = blockSumF(lS, s_fred, tid);
        float E1 = blockSumF(lE, s_fred, tid);
        float vstar = unmonof((unsigned)lo);
        float n2 = (float)(NNEG - k1);
        Sneg = S1 + n2 * vstar;
        Sexp = E1 + n2 * expf(vstar - M);
    } else {
        // exact fallback (massive ties): binary search with full-row scans
        unsigned long long lo = (unsigned long long)monof(theta);
        unsigned long long hi = 0xffffffffull;
        while (lo < hi) {
            unsigned long long mid = lo + (hi - lo + 1) / 2;
            int lc = 0;
            for (int i = tid; i < CDIM / 8; i += 256) {
                int base = i * 8;
                uint4 v4 = *(const uint4*)(rp + base);
                unsigned ws[4] = {v4.x, v4.y, v4.z, v4.w};
#pragma unroll
                for (int q = 0; q < 4; q++) {
                    float2 f = __half22float2(*(__half2*)&ws[q]);
                    int c0 = base + 2 * q, c1 = c0 + 1;
                    if (c0 != lab) lc += ((unsigned long long)monof(f.x) >= mid);
                    if (c1 != lab) lc += ((unsigned long long)monof(f.y) >= mid);
                }
            }
            int tot = blockSumI(lc, s_ired, tid);
            if (tot >= NNEG) lo = mid; else hi = mid - 1;
        }
        unsigned long long ucut = lo + 1;
        int lk1 = 0; float lS = 0.f, lE = 0.f;
        for (int i = tid; i < CDIM / 8; i += 256) {
            int base = i * 8;
            uint4 v4 = *(const uint4*)(rp + base);
            unsigned ws[4] = {v4.x, v4.y, v4.z, v4.w};
#pragma unroll
            for (int q = 0; q < 4; q++) {
                float2 f = __half22float2(*(__half2*)&ws[q]);
                int c0 = base + 2 * q, c1 = c0 + 1;
                if (c0 != lab && (unsigned long long)monof(f.x) >= ucut) { lk1++; lS += f.x; lE += expf(f.x - M); }
                if (c1 != lab && (unsigned long long)monof(f.y) >= ucut) { lk1++; lS += f.y; lE += expf(f.y - M); }
            }
        }
        int k1 = blockSumI(lk1, s_ired, tid);
        float S1 = blockSumF(lS, s_fred, tid);
        float E1 = blockSumF(lE, s_fred, tid);
        float vstar = unmonof((unsigned)lo);
        float n2 = (float)(NNEG - k1);
        Sneg = S1 + n2 * vstar;
        Sexp = E1 + n2 * expf(vstar - M);
    }

    if (tid == 0) {
        float lse = M + logf(Sexp + expf(posv - M));
        // targets: t0 = 0.9 + 0.1/500 = 0.9002, tj = 0.0002 (x50), sum = 0.9102
        g_rowloss[row] = 0.9102f * lse - 0.9002f * posv - 0.0002f * Sneg;
    }
}

// ===========================================================================
// Kernel 3: mean over rows -> scalar
// ===========================================================================
__global__ void k_final(float* __restrict__ out) {
    __shared__ float s[256];
    int tid = threadIdx.x;
    float a = 0.f;
    for (int i = tid; i < B_ROWS; i += 256) a += g_rowloss[i];
    s[tid] = a;
    __syncthreads();
    for (int st = 128; st > 0; st >>= 1) {
        if (tid < st) s[tid] += s[tid + st];
        __syncthreads();
    }
    if (tid == 0) out[0] = s[0] * (1.0f / (float)B_ROWS);
}

// ===========================================================================
extern "C" void kernel_launch(void* const* d_in, const int* in_sizes, int n_in,
                              void* d_out, int out_size) {
    const float* f = nullptr;
    const float* cen = nullptr;
    const void* lab = nullptr;
    for (int i = 0; i < n_in; i++) {
        long long sz = in_sizes[i];
        if (sz == (long long)B_ROWS * DK) f = (const float*)d_in[i];
        else if (sz == (long long)CDIM * DK) cen = (const float*)d_in[i];
        else if (sz == (long long)B_ROWS) lab = d_in[i];
    }
    if (!f) f = (const float*)d_in[0];
    if (!cen) cen = (const float*)d_in[1];
    if (!lab) lab = d_in[2];

    const int SMEM_SZ = 6 * 16384;  // six stages of (A|B), 96KB/CTA
    static int s_attr_done = 0;
    if (!s_attr_done) {
        cudaFuncSetAttribute(k_gemm_mma,
                             cudaFuncAttributeMaxDynamicSharedMemorySize, SMEM_SZ);
        s_attr_done = 1;
    }

    __half *ah, *bh;
    cudaGetSymbolAddress((void**)&ah, g_ah);
    cudaGetSymbolAddress((void**)&bh, g_bh);

    k_declab<<<1, 256>>>(lab);
    k_conv<<<(B_ROWS * DK) / (256 * 4), 256>>>(f, ah);
    k_conv<<<(CDIM * DK) / (256 * 4), 256>>>(cen, bh);
    dim3 grid(16, 512);  // x = M tiles (co-resident CTAs share a B tile), y = N
    k_gemm_mma<<<grid, 256, SMEM_SZ>>>();
    k_topk<<<B_ROWS, 256>>>();
    k_final<<<1, 256>>>((float*)d_out);
}